// round 8
// baseline (speedup 1.0000x reference)
#include <cuda_runtime.h>
#include <cuda_bf16.h>
#include <math.h>
#include <stdint.h>

// Problem dims (fixed)
#define B_ 64
#define D_ 512
#define M_ 1024
#define L_ 256
#define KK_ 30

typedef __nv_bfloat16 bf16;

// ===================== device scratch =========================================
__device__ float g_Wv_f[32 * D_];
__device__ float g_Wq_f[32 * D_];
__device__ float g_WqQ[2 * (long)B_ * 32 * L_];   // partial pair
__device__ float g_P  [2 * (long)B_ * 32 * D_];
__device__ float g_Yv [2 * (long)B_ * 32 * D_];
__device__ float g_WvV[(long)B_ * 32 * M_];       // unsplit (K45)
__device__ float g_Yq [2 * (long)B_ * 32 * D_];
__device__ float g_R  [2 * (long)B_ * 32 * D_];
__device__ float g_Tq [2 * (long)B_ * 32 * L_];
__device__ float g_zv[B_ * M_];
__device__ float g_zq[B_ * L_];
__device__ float g_v1[B_ * D_];
__device__ float g_q1[B_ * D_];

// ===================== helpers ================================================
__device__ __forceinline__ uint32_t s2u(const void* p) {
    return (uint32_t)__cvta_generic_to_shared(p);
}
__device__ __forceinline__ void ldsm4(uint32_t* r, uint32_t addr) {
    asm volatile("ldmatrix.sync.aligned.m8n8.x4.shared.b16 {%0,%1,%2,%3}, [%4];"
                 : "=r"(r[0]), "=r"(r[1]), "=r"(r[2]), "=r"(r[3]) : "r"(addr));
}
__device__ __forceinline__ void ldsm4t(uint32_t* r, uint32_t addr) {
    asm volatile("ldmatrix.sync.aligned.m8n8.x4.trans.shared.b16 {%0,%1,%2,%3}, [%4];"
                 : "=r"(r[0]), "=r"(r[1]), "=r"(r[2]), "=r"(r[3]) : "r"(addr));
}
__device__ __forceinline__ void mma_bf(float* d, const uint32_t* a, const uint32_t* b) {
    asm volatile(
        "mma.sync.aligned.m16n8k16.row.col.f32.bf16.bf16.f32 "
        "{%0,%1,%2,%3}, {%4,%5,%6,%7}, {%8,%9}, {%0,%1,%2,%3};"
        : "+f"(d[0]), "+f"(d[1]), "+f"(d[2]), "+f"(d[3])
        : "r"(a[0]), "r"(a[1]), "r"(a[2]), "r"(a[3]), "r"(b[0]), "r"(b[1]));
}
__device__ __forceinline__ void split_bf(float x, bf16& h, bf16& l) {
    h = __float2bfloat16(x);
    l = __float2bfloat16(x - __bfloat162float(h));
}

// smem layout constants (bytes)
#define A_BUF 10240      // slot: AN 128x80B; TRA 32x272B (8704 <= slot)
#define B_BUF 2560       // 32 x 40 bf16
#define BS_OFF 40960     // after 4 A slots
#define CST 132          // epilogue staging n-stride (floats)

// ===================== weight pad (fp32) ======================================
__global__ void conv_pad_f(const float* __restrict__ Wv, float* __restrict__ WvP,
                           const float* __restrict__ Wq, float* __restrict__ WqP)
{
    int idx = blockIdx.x * blockDim.x + threadIdx.x;
    if (idx >= 32 * D_) return;
    int k = idx / D_, d = idx % D_;
    WvP[idx] = (k < KK_) ? Wv[k * D_ + d] : 0.f;
    WqP[idx] = (k < KK_) ? Wq[k * D_ + d] : 0.f;
}

// ===================== HMMA GEMM, fp32 partial I/O ============================
// Ct[128-row m-tile of Nbig][32] = A(fp32) x S[32,Kd]^T
// S supplied as fp32 partial pair (b may be null); summed+split to bf16 hi/lo at
// staging. Split-K via blockIdx.z (nsplit), output partial s at C + s*partC.
struct GJob {
    const float* A; int lda; long sA;
    const float* B0a; const float* B0b; long sB0;
    const float* B1a; const float* B1b; long sB1;
    float* C; long sC; long partC;
    const float* w; float* z;
    int Nbig, Kd, nsplit;
};

// EPI: 0 = write acc0 fp32 partial; 2 = (NB=2, nsplit=1) write acc0 fp32 + fused logits
template<int NB, int EPI, bool TRA>
__global__ void __launch_bounds__(256) tc_gemm(GJob j)
{
    extern __shared__ char smem[];
    const uint32_t sb = s2u(smem);
    float* smw = (float*)(smem + BS_OFF + NB * 4 * B_BUF);

    const int tid = threadIdx.x;
    const int w = tid >> 5, lane = tid & 31;
    const int b = blockIdx.y;
    const int m0 = blockIdx.x * 128;
    const int split = blockIdx.z;

    const float* Ab = j.A + (long)b * j.sA;
    const float* BpA[NB];
    const float* BpB[NB];
    BpA[0] = j.B0a + (long)b * j.sB0;
    BpB[0] = j.B0b ? j.B0b + (long)b * j.sB0 : nullptr;
    if (NB == 2) {
        BpA[1] = j.B1a + (long)b * j.sB1;
        BpB[1] = j.B1b ? j.B1b + (long)b * j.sB1 : nullptr;
    }

    if (EPI == 2 && tid < KK_) smw[tid] = j.w[tid];

    // A addressing
    const float* aptr = TRA
        ? (Ab + (long)(tid >> 3) * j.lda + m0 + (tid & 7) * 16)
        : (Ab + (long)(m0 + (tid >> 1)) * j.lda + (tid & 1) * 16);
    const int aSts = TRA ? ((tid >> 3) * 272 + (tid & 7) * 32)
                         : ((tid >> 1) * 80 + (tid & 1) * 32);
    // B addressing: 32 rows x 8 float4 cols
    const int brow = tid >> 3, bcg = tid & 7;

    const int Titer = j.Kd / 32 / j.nsplit;
    const int t0 = split * Titer;

    float4 fr[4];
    float4 brr[NB];

    auto loadA = [&](int t) {
        const float* p = TRA ? (aptr + (long)t * 32 * j.lda) : (aptr + t * 32);
        fr[0] = *(const float4*)p;
        fr[1] = *(const float4*)(p + 4);
        fr[2] = *(const float4*)(p + 8);
        fr[3] = *(const float4*)(p + 12);
    };
    auto loadB = [&](int t) {
#pragma unroll
        for (int nb = 0; nb < NB; nb++) {
            long off = (long)brow * j.Kd + t * 32 + bcg * 4;
            float4 v = *(const float4*)(BpA[nb] + off);
            if (BpB[nb]) {
                float4 u = *(const float4*)(BpB[nb] + off);
                v.x += u.x; v.y += u.y; v.z += u.z; v.w += u.w;
            }
            brr[nb] = v;
        }
    };
    auto stsA = [&](int s) {
        uint32_t hp[8], lp[8];
        const float* f = (const float*)fr;
#pragma unroll
        for (int i = 0; i < 8; i++) {
            bf16 h0, l0, h1, l1;
            split_bf(f[2 * i], h0, l0);
            split_bf(f[2 * i + 1], h1, l1);
            hp[i] = (uint32_t)*(uint16_t*)&h0 | ((uint32_t)*(uint16_t*)&h1 << 16);
            lp[i] = (uint32_t)*(uint16_t*)&l0 | ((uint32_t)*(uint16_t*)&l1 << 16);
        }
        char* d0 = smem + (s * 2 + 0) * A_BUF + aSts;
        char* d1 = smem + (s * 2 + 1) * A_BUF + aSts;
        *(uint4*)d0        = make_uint4(hp[0], hp[1], hp[2], hp[3]);
        *(uint4*)(d0 + 16) = make_uint4(hp[4], hp[5], hp[6], hp[7]);
        *(uint4*)d1        = make_uint4(lp[0], lp[1], lp[2], lp[3]);
        *(uint4*)(d1 + 16) = make_uint4(lp[4], lp[5], lp[6], lp[7]);
    };
    auto stsB = [&](int s) {
#pragma unroll
        for (int nb = 0; nb < NB; nb++) {
            float4 v = brr[nb];
            bf16 h0, l0, h1, l1, h2, l2, h3, l3;
            split_bf(v.x, h0, l0); split_bf(v.y, h1, l1);
            split_bf(v.z, h2, l2); split_bf(v.w, h3, l3);
            uint32_t hA = (uint32_t)*(uint16_t*)&h0 | ((uint32_t)*(uint16_t*)&h1 << 16);
            uint32_t hB = (uint32_t)*(uint16_t*)&h2 | ((uint32_t)*(uint16_t*)&h3 << 16);
            uint32_t lA = (uint32_t)*(uint16_t*)&l0 | ((uint32_t)*(uint16_t*)&l1 << 16);
            uint32_t lB = (uint32_t)*(uint16_t*)&l2 | ((uint32_t)*(uint16_t*)&l3 << 16);
            char* d = smem + BS_OFF + ((s * NB + nb) * 2 + 0) * B_BUF + brow * 80 + bcg * 8;
            *(uint2*)d           = make_uint2(hA, hB);
            *(uint2*)(d + B_BUF) = make_uint2(lA, lB);
        }
    };

    // ldmatrix lane addressing
    const uint32_t aLane = TRA
        ? (uint32_t)((((lane & 7) + 8 * (lane >> 4)) * 272) + (w * 16 + ((lane >> 3) & 1) * 8) * 2)
        : (uint32_t)((w * 16 + (lane & 15)) * 80 + (lane >> 4) * 16);
    const uint32_t aKs = TRA ? 4352u : 32u;
    const uint32_t bLaneRow = (uint32_t)((((lane >> 4) & 1) * 8 + (lane & 7)) * 80
                                         + ((lane >> 3) & 1) * 16);

    float acc[NB][4][4];
#pragma unroll
    for (int nb = 0; nb < NB; nb++)
#pragma unroll
        for (int nt = 0; nt < 4; nt++)
#pragma unroll
            for (int r = 0; r < 4; r++) acc[nb][nt][r] = 0.f;

    // prologue: tile t0 into slot 0
    loadA(t0); loadB(t0);
    stsA(0);   stsB(0);

    for (int it = 0; it < Titer; it++) {
        const int s = it & 1;
        __syncthreads();   // slot s (staged last iter) visible; slot s^1 free

        if (it + 1 < Titer) { loadA(t0 + it + 1); loadB(t0 + it + 1); }

        const uint32_t aH = sb + (uint32_t)((s * 2 + 0) * A_BUF) + aLane;
        const uint32_t aL = aH + A_BUF;

#pragma unroll
        for (int ks = 0; ks < 2; ks++) {
            uint32_t ah[4], al[4];
            if (TRA) { ldsm4t(ah, aH + ks * aKs); ldsm4t(al, aL + ks * aKs); }
            else     { ldsm4 (ah, aH + ks * aKs); ldsm4 (al, aL + ks * aKs); }
#pragma unroll
            for (int nb = 0; nb < NB; nb++) {
#pragma unroll
                for (int p = 0; p < 2; p++) {
                    uint32_t bbase = sb + (uint32_t)(BS_OFF
                        + ((s * NB + nb) * 2 + 0) * B_BUF
                        + p * 16 * 80) + bLaneRow + ks * 32;
                    uint32_t bh[4], bl[4];
                    ldsm4(bh, bbase);
                    ldsm4(bl, bbase + B_BUF);
                    mma_bf(acc[nb][2 * p],     ah, &bh[0]);
                    mma_bf(acc[nb][2 * p],     ah, &bl[0]);
                    mma_bf(acc[nb][2 * p],     al, &bh[0]);
                    mma_bf(acc[nb][2 * p + 1], ah, &bh[2]);
                    mma_bf(acc[nb][2 * p + 1], ah, &bl[2]);
                    mma_bf(acc[nb][2 * p + 1], al, &bh[2]);
                }
            }
        }

        if (it + 1 < Titer) { stsA((it + 1) & 1); stsB((it + 1) & 1); }
    }

    // ---------------- epilogue --------------------------------------------
    __syncthreads();
    float* Cs = (float*)smem;
    {
        const int g = lane >> 2, cc = lane & 3;
        const int m_l = w * 16 + g;
#pragma unroll
        for (int nb = 0; nb < NB; nb++) {
            float* C_ = Cs + nb * 32 * CST;
#pragma unroll
            for (int nt = 0; nt < 4; nt++) {
                int n0 = nt * 8 + cc * 2;
                C_[(n0 + 0) * CST + m_l]     = acc[nb][nt][0];
                C_[(n0 + 1) * CST + m_l]     = acc[nb][nt][1];
                C_[(n0 + 0) * CST + m_l + 8] = acc[nb][nt][2];
                C_[(n0 + 1) * CST + m_l + 8] = acc[nb][nt][3];
            }
        }
    }
    __syncthreads();

    // write acc0 tile fp32 (coalesced)
    {
        float* Co = j.C + (long)split * j.partC + (long)b * j.sC;
#pragma unroll
        for (int it = 0; it < 4; it++) {
            int q = tid + it * 256;
            int n = q >> 5, m4 = (q & 31) * 4;
            *(float4*)(Co + (long)n * j.Nbig + m0 + m4) = *(float4*)&Cs[n * CST + m4];
        }
    }
    if (EPI == 2) {
        if (tid < 128) {
            float zacc = 0.f;
#pragma unroll
            for (int k = 0; k < KK_; k++)
                zacc += smw[k] * tanhf(Cs[k * CST + tid] + Cs[(32 + k) * CST + tid]);
            j.z[(long)b * j.Nbig + m0 + tid] = zacc;
        }
    }
}

// ===================== logits from 4 partial arrays ===========================
__global__ void logits4(const float* __restrict__ X0, const float* __restrict__ X1,
                        const float* __restrict__ T0, const float* __restrict__ T1,
                        const float* __restrict__ w, float* __restrict__ z, int n)
{
    int idx = blockIdx.x * blockDim.x + threadIdx.x;
    if (idx >= B_ * n) return;
    int b = idx / n, m = idx - b * n;
    long base = (long)b * 32 * n + m;
    float acc = 0.f;
#pragma unroll
    for (int k = 0; k < KK_; k++) {
        long o = base + (long)k * n;
        acc += __ldg(&w[k]) * tanhf(X0[o] + X1[o] + T0[o] + T1[o]);
    }
    z[idx] = acc;
}

// ===================== tail kernels ===========================================
__global__ void softmax_kernel(float* __restrict__ z, int n)
{
    const int b = blockIdx.x;
    float* row = z + (long)b * n;
    __shared__ float red[256];
    const int tid = threadIdx.x;

    float mx = -1e30f;
    for (int i = tid; i < n; i += 256) mx = fmaxf(mx, row[i]);
    red[tid] = mx; __syncthreads();
    for (int s = 128; s > 0; s >>= 1) {
        if (tid < s) red[tid] = fmaxf(red[tid], red[tid + s]);
        __syncthreads();
    }
    mx = red[0]; __syncthreads();

    float sum = 0.f;
    for (int i = tid; i < n; i += 256) {
        float e = expf(row[i] - mx);
        row[i] = e;
        sum += e;
    }
    red[tid] = sum; __syncthreads();
    for (int s = 128; s > 0; s >>= 1) {
        if (tid < s) red[tid] += red[tid + s];
        __syncthreads();
    }
    float inv = 1.f / red[0];
    for (int i = tid; i < n; i += 256) row[i] *= inv;
}

__global__ void pool_v_kernel(const float* __restrict__ V,
                              const float* __restrict__ a,
                              float* __restrict__ v1)
{
    const int b = blockIdx.y;
    const int warp = threadIdx.x >> 5;
    const int lane = threadIdx.x & 31;
    const int d = blockIdx.x * 8 + warp;
    const float4* vr = reinterpret_cast<const float4*>(V + ((long)b * D_ + d) * M_);
    const float4* ar = reinterpret_cast<const float4*>(a + (long)b * M_);
    float acc = 0.f;
#pragma unroll
    for (int i = 0; i < M_ / 128; i++) {
        float4 v = vr[i * 32 + lane];
        float4 w = ar[i * 32 + lane];
        acc += v.x * w.x + v.y * w.y + v.z * w.z + v.w * w.w;
    }
#pragma unroll
    for (int o = 16; o > 0; o >>= 1) acc += __shfl_down_sync(0xffffffffu, acc, o);
    if (lane == 0) v1[b * D_ + d] = acc;
}

__global__ void pool_q_kernel(const float* __restrict__ Q,
                              const float* __restrict__ a,
                              float* __restrict__ q1)
{
    const int b = blockIdx.x;
    __shared__ float as[L_];
    for (int i = threadIdx.x; i < L_; i += blockDim.x) as[i] = a[b * L_ + i];
    __syncthreads();
    const int d = threadIdx.x;
    const float* qb = Q + (long)b * L_ * D_;
    float acc = 0.f;
#pragma unroll 8
    for (int l = 0; l < L_; l++) acc += as[l] * qb[(long)l * D_ + d];
    q1[b * D_ + d] = acc;
}

__global__ void bcast_kernel(float4* __restrict__ out,
                             const float4* __restrict__ src,
                             int rows)
{
    const long total4 = (long)B_ * rows * (D_ / 4);
    long i = (long)blockIdx.x * blockDim.x + threadIdx.x;
    if (i >= total4) return;
    int d4 = (int)(i % (D_ / 4));
    long br = i / (D_ / 4);
    int b = (int)(br / rows);
    out[i] = __ldg(&src[(long)b * (D_ / 4) + d4]);
}

// ===================== launch =================================================
extern "C" void kernel_launch(void* const* d_in, const int* in_sizes, int n_in,
                              void* d_out, int out_size)
{
    const float* V   = (const float*)d_in[0];  // [B, D, M]
    const float* Q   = (const float*)d_in[1];  // [B, L, D]
    const float* W_b = (const float*)d_in[2];  // [D, D]
    const float* W_v = (const float*)d_in[3];  // [K, D]
    const float* W_q = (const float*)d_in[4];  // [K, D]
    const float* whv = (const float*)d_in[5];  // [K]
    const float* whq = (const float*)d_in[6];  // [K]
    float* out = (float*)d_out;

    float *pWv_f, *pWq_f, *pWqQ, *pP, *pYv, *pWvV, *pYq, *pR, *pTq;
    float *p_zv, *p_zq, *p_v1, *p_q1;
    cudaGetSymbolAddress((void**)&pWv_f, g_Wv_f);
    cudaGetSymbolAddress((void**)&pWq_f, g_Wq_f);
    cudaGetSymbolAddress((void**)&pWqQ, g_WqQ);
    cudaGetSymbolAddress((void**)&pP,   g_P);
    cudaGetSymbolAddress((void**)&pYv,  g_Yv);
    cudaGetSymbolAddress((void**)&pWvV, g_WvV);
    cudaGetSymbolAddress((void**)&pYq,  g_Yq);
    cudaGetSymbolAddress((void**)&pR,   g_R);
    cudaGetSymbolAddress((void**)&pTq,  g_Tq);
    cudaGetSymbolAddress((void**)&p_zv, g_zv);
    cudaGetSymbolAddress((void**)&p_zq, g_zq);
    cudaGetSymbolAddress((void**)&p_v1, g_v1);
    cudaGetSymbolAddress((void**)&p_q1, g_q1);

    const long PL = (long)B_ * 32 * L_;   // partial stride (L-sized outputs)
    const long PD = (long)B_ * 32 * D_;   // partial stride (D-sized outputs)
    const long sQ = (long)L_ * D_;
    const long sV = (long)D_ * M_;

    const int SM1 = BS_OFF + 1 * 4 * B_BUF + 128;  // 51328
    const int SM2 = BS_OFF + 2 * 4 * B_BUF + 128;  // 61568
    cudaFuncSetAttribute(tc_gemm<1, 0, false>, cudaFuncAttributeMaxDynamicSharedMemorySize, SM1);
    cudaFuncSetAttribute(tc_gemm<1, 0, true>,  cudaFuncAttributeMaxDynamicSharedMemorySize, SM1);
    cudaFuncSetAttribute(tc_gemm<2, 2, true>,  cudaFuncAttributeMaxDynamicSharedMemorySize, SM2);

    conv_pad_f<<<(32 * D_ + 255) / 256, 256>>>(W_v, pWv_f, W_q, pWq_f);

    GJob j;

    // K1: WqQ[k,l] = sum_d Wq[k,d] Q[l,d] : A=Q AN; B0=Wq_f single; split 2
    j = { Q, D_, sQ,  pWv_f, nullptr, 0,  nullptr, nullptr, 0,
          pWqQ, (long)32 * L_, PL,  nullptr, nullptr,  L_, D_, 2 };
    j.B0a = pWq_f;
    tc_gemm<1, 0, false><<<dim3(L_ / 128, B_, 2), 256, SM1>>>(j);

    // K2: P[k,e] = sum_l WqQ[k,l] Q[l,e] : A=Q TRA; B0=WqQ pair; split 2
    j = { Q, D_, sQ,  pWqQ, pWqQ + PL, (long)32 * L_,  nullptr, nullptr, 0,
          pP, (long)32 * D_, PD,  nullptr, nullptr,  D_, L_, 2 };
    tc_gemm<1, 0, true><<<dim3(D_ / 128, B_, 2), 256, SM1>>>(j);

    // K3: Yv[k,e] = sum_d P[k,d] Wb[d,e] : A=Wb TRA (no batch); B0=P pair; split 2
    j = { W_b, D_, 0,  pP, pP + PD, (long)32 * D_,  nullptr, nullptr, 0,
          pYv, (long)32 * D_, PD,  nullptr, nullptr,  D_, D_, 2 };
    tc_gemm<1, 0, true><<<dim3(D_ / 128, B_, 2), 256, SM1>>>(j);

    // K45: A=V TRA; B0=Wv_f single -> WvV (fp32, unsplit); B1=Yv pair -> Tv;
    //      fused logits_v. nsplit=1.
    j = { V, M_, sV,  pWv_f, nullptr, 0,  pYv, pYv + PD, (long)32 * D_,
          pWvV, (long)32 * M_, 0,  whv, p_zv,  M_, D_, 1 };
    tc_gemm<2, 2, true><<<dim3(M_ / 128, B_, 1), 256, SM2>>>(j);

    // K6: Yq[k,e] = sum_m WvV[k,m] V[e,m] : A=V AN; B0=WvV single; split 2
    j = { V, M_, sV,  pWvV, nullptr, (long)32 * M_,  nullptr, nullptr, 0,
          pYq, (long)32 * D_, PD,  nullptr, nullptr,  D_, M_, 2 };
    tc_gemm<1, 0, false><<<dim3(D_ / 128, B_, 2), 256, SM1>>>(j);

    // K7: R[k,d] = sum_e Yq[k,e] Wb[d,e] : A=Wb AN (no batch); B0=Yq pair; split 2
    j = { W_b, D_, 0,  pYq, pYq + PD, (long)32 * D_,  nullptr, nullptr, 0,
          pR, (long)32 * D_, PD,  nullptr, nullptr,  D_, D_, 2 };
    tc_gemm<1, 0, false><<<dim3(D_ / 128, B_, 2), 256, SM1>>>(j);

    // K8: Tq[k,l] = sum_d R[k,d] Q[l,d] : A=Q AN; B0=R pair; split 2
    j = { Q, D_, sQ,  pR, pR + PD, (long)32 * D_,  nullptr, nullptr, 0,
          pTq, (long)32 * L_, PL,  nullptr, nullptr,  L_, D_, 2 };
    tc_gemm<1, 0, false><<<dim3(L_ / 128, B_, 2), 256, SM1>>>(j);

    // logits_q: z = sum_k w*tanh(WqQ0+WqQ1 + Tq0+Tq1)
    logits4<<<(B_ * L_ + 255) / 256, 256>>>(
        pWqQ, pWqQ + PL, pTq, pTq + PL, whq, p_zq, L_);

    // softmax
    softmax_kernel<<<B_, 256>>>(p_zv, M_);
    softmax_kernel<<<B_, 256>>>(p_zq, L_);

    // pooled vectors
    {
        dim3 grid(D_ / 8, B_);
        pool_v_kernel<<<grid, 256>>>(V, p_zv, p_v1);
    }
    pool_q_kernel<<<B_, 512>>>(Q, p_zq, p_q1);

    // broadcast outputs: v [B,M,D] then q [B,L,D]
    {
        long n4v = (long)B_ * M_ * (D_ / 4);
        bcast_kernel<<<(unsigned)((n4v + 255) / 256), 256>>>(
            (float4*)out, (const float4*)p_v1, M_);
        long n4q = (long)B_ * L_ * (D_ / 4);
        float* out_q = out + (long)B_ * M_ * D_;
        bcast_kernel<<<(unsigned)((n4q + 255) / 256), 256>>>(
            (float4*)out_q, (const float4*)p_q1, L_);
    }
}